// round 1
// baseline (speedup 1.0000x reference)
#include <cuda_runtime.h>
#include <math.h>

// ---------------- constants ----------------
constexpr int DIMX  = 512;
constexpr int NSEQ  = 256;
constexpr int ROWS1 = 16384;            // B*N = 64*256
constexpr int ROWS3 = 3 * ROWS1;        // q,k,v stacked
constexpr size_t FS = (size_t)ROWS1 * DIMX;   // 8388608 floats per tensor

// ---------------- scratch (static device memory; no allocs) ----------------
__device__ float g_xn[3 * FS];                    // LN output, 3 tensors
__device__ float g_f [3 * FS];                    // projected features
__device__ float g_s [(size_t)512 * NSEQ * NSEQ]; // per-(h,b) score matrices
__device__ float g_att[FS];                       // attention output in [B,N,h*d]
__device__ float g_norms[2 * 512 * NSEQ];         // qn, kn
__device__ float g_vc[256];                       // [Vq(64), Cq(64), Vk(64), Ck(64)]

__device__ __forceinline__ float warp_sum(float v) {
    #pragma unroll
    for (int o = 16; o; o >>= 1) v += __shfl_xor_sync(0xffffffffu, v, o);
    return v;
}

// ---------------- 1) LayerNorm: one warp per row ----------------
__global__ __launch_bounds__(256) void ln_kernel(
    const float* __restrict__ q, const float* __restrict__ k, const float* __restrict__ v,
    const float* __restrict__ gma, const float* __restrict__ bta)
{
    int warp = threadIdx.x >> 5, lane = threadIdx.x & 31;
    int row = blockIdx.x * 8 + warp;          // 0..49151
    int t = row >> 14;                        // which tensor
    int r = row & 16383;
    const float* src = (t == 0 ? q : (t == 1 ? k : v)) + (size_t)r * DIMX;

    float x[16];
    float s = 0.f;
    #pragma unroll
    for (int i = 0; i < 16; i++) { x[i] = src[lane + 32 * i]; s += x[i]; }
    s = warp_sum(s);
    float mu = s * (1.f / 512.f);
    float ss = 0.f;
    #pragma unroll
    for (int i = 0; i < 16; i++) { float d = x[i] - mu; ss += d * d; }
    ss = warp_sum(ss);
    float rs = rsqrtf(ss * (1.f / 512.f) + 1e-5f);

    float* dst = g_xn + (size_t)row * DIMX;
    #pragma unroll
    for (int i = 0; i < 16; i++) {
        int c = lane + 32 * i;
        dst[c] = (x[i] - mu) * rs * gma[c] + bta[c];
    }
}

// ---------------- 2/7) SGEMM 128x128x8, 8x8 per thread, N=K=512 ----------------
__global__ __launch_bounds__(256) void sgemm_kernel(
    const float* __restrict__ A, const float* __restrict__ B,
    float* __restrict__ C, const float* __restrict__ bias)
{
    constexpr int BM = 128, BN = 128, BK = 8, TM = 8, TN = 8;
    constexpr int N = 512, K = 512;
    __shared__ float As[BK * BM];   // transposed
    __shared__ float Bs[BK * BN];

    int tid = threadIdx.x;
    A += (size_t)blockIdx.y * BM * K;
    B += (size_t)blockIdx.x * BN;
    C += (size_t)blockIdx.y * BM * N + (size_t)blockIdx.x * BN;

    int tCol = tid & 15;      // 0..15
    int tRow = tid >> 4;      // 0..15
    int iRA = tid >> 1, iCA = tid & 1;     // A loads: 128 rows x 8 cols
    int iRB = tid >> 5, iCB = tid & 31;    // B loads: 8 rows x 128 cols

    float acc[TM][TN] = {};
    float rM[TM], rN[TN];

    for (int bk = 0; bk < K; bk += BK) {
        float4 a4 = *(const float4*)(A + (size_t)iRA * K + iCA * 4);
        As[(iCA * 4 + 0) * BM + iRA] = a4.x;
        As[(iCA * 4 + 1) * BM + iRA] = a4.y;
        As[(iCA * 4 + 2) * BM + iRA] = a4.z;
        As[(iCA * 4 + 3) * BM + iRA] = a4.w;
        *(float4*)&Bs[iRB * BN + iCB * 4] = *(const float4*)(B + (size_t)iRB * N + iCB * 4);
        __syncthreads();
        A += BK;
        B += (size_t)BK * N;
        #pragma unroll
        for (int k = 0; k < BK; k++) {
            #pragma unroll
            for (int i = 0; i < TM; i++) rM[i] = As[k * BM + tRow * TM + i];
            #pragma unroll
            for (int j = 0; j < TN; j++) rN[j] = Bs[k * BN + tCol * TN + j];
            #pragma unroll
            for (int i = 0; i < TM; i++)
                #pragma unroll
                for (int j = 0; j < TN; j++)
                    acc[i][j] += rM[i] * rN[j];
        }
        __syncthreads();
    }

    #pragma unroll
    for (int i = 0; i < TM; i++) {
        #pragma unroll
        for (int j = 0; j < TN; j += 4) {
            int col = tCol * TN + j;
            float4 o = make_float4(acc[i][j], acc[i][j + 1], acc[i][j + 2], acc[i][j + 3]);
            if (bias) {
                const float* bp = bias + blockIdx.x * BN + col;
                o.x += bp[0]; o.y += bp[1]; o.z += bp[2]; o.w += bp[3];
            }
            *(float4*)(C + (size_t)(tRow * TM + i) * N + col) = o;
        }
    }
}

// ---------------- 3) row norms of f_q, f_k: one warp per (t,hb,n) ----------------
__global__ __launch_bounds__(256) void norm_kernel()
{
    int warp = threadIdx.x >> 5, lane = threadIdx.x & 31;
    int gid = blockIdx.x * 8 + warp;       // 0..262143
    int t = gid >> 17;
    int rem = gid & 131071;
    int hb = rem >> 8, n = rem & 255;
    int h = hb >> 6, b = hb & 63;
    const float* base = g_f + (size_t)t * FS + (size_t)(b * 256 + n) * 512 + h * 64;
    float v0 = base[lane], v1 = base[lane + 32];
    float ss = warp_sum(v0 * v0 + v1 * v1);
    if (!lane) g_norms[gid] = sqrtf(ss);
}

// ---------------- 4) chunk statistics: one block per (tensor, chunk) ----------------
__global__ __launch_bounds__(256) void stats_kernel()
{
    __shared__ float sE[128 * 64];
    __shared__ float smu[64];
    __shared__ float red[256];

    int tid = threadIdx.x;
    int t = blockIdx.x >> 6;        // 0=q, 1=k
    int c = blockIdx.x & 63;        // chunk id
    int h = c >> 3;
    const float* fb = g_f + (size_t)t * FS;

    int ti = tid >> 4, tj = tid & 15;
    float accC = 0.f, accV = 0.f;   // thread 0 accumulates

    for (int s = 0; s < 8; s++) {
        int b = ((c & 7) << 3) + s;
        const float* base = fb + (size_t)(b * 256) * 512 + h * 64;

        // column means over N=256
        int i = tid & 63, grp = tid >> 6;
        float sm = 0.f;
        for (int n = grp; n < 256; n += 4) sm += base[(size_t)n * 512 + i];
        red[tid] = sm;
        __syncthreads();
        if (tid < 64)
            smu[tid] = (red[tid] + red[tid + 64] + red[tid + 128] + red[tid + 192]) * (1.f / 256.f);
        __syncthreads();

        // Gram matrix G = centered^T centered, accumulated over 2 chunks of 128 rows
        float acc[4][4] = {};
        for (int ch = 0; ch < 2; ch++) {
            for (int idx = tid; idx < 128 * 64; idx += 256) {
                int n = idx >> 6, ii = idx & 63;
                sE[idx] = base[(size_t)(ch * 128 + n) * 512 + ii] - smu[ii];
            }
            __syncthreads();
            #pragma unroll 8
            for (int n = 0; n < 128; n++) {
                float4 a  = *(const float4*)&sE[n * 64 + ti * 4];
                float4 bb = *(const float4*)&sE[n * 64 + tj * 4];
                acc[0][0] += a.x * bb.x; acc[0][1] += a.x * bb.y; acc[0][2] += a.x * bb.z; acc[0][3] += a.x * bb.w;
                acc[1][0] += a.y * bb.x; acc[1][1] += a.y * bb.y; acc[1][2] += a.y * bb.z; acc[1][3] += a.y * bb.w;
                acc[2][0] += a.z * bb.x; acc[2][1] += a.z * bb.y; acc[2][2] += a.z * bb.z; acc[2][3] += a.z * bb.w;
                acc[3][0] += a.w * bb.x; acc[3][1] += a.w * bb.y; acc[3][2] += a.w * bb.z; acc[3][3] += a.w * bb.w;
            }
            __syncthreads();
        }

        float tot = 0.f;
        #pragma unroll
        for (int r = 0; r < 4; r++)
            #pragma unroll
            for (int r2 = 0; r2 < 4; r2++) tot += acc[r][r2] * acc[r][r2];
        float dsum = 0.f, vsum = 0.f;
        if (ti == tj) {
            #pragma unroll
            for (int r = 0; r < 4; r++) {
                float gii = acc[r][r];
                dsum += gii * gii;
                float sig = sqrtf(gii * (1.f / 255.f) + 1e-8f);
                vsum += fmaxf(0.f, 1.f - sig);
            }
        }

        // three block reductions
        red[tid] = tot; __syncthreads();
        for (int st = 128; st; st >>= 1) { if (tid < st) red[tid] += red[tid + st]; __syncthreads(); }
        if (tid == 0) accC += red[0];
        __syncthreads();
        red[tid] = dsum; __syncthreads();
        for (int st = 128; st; st >>= 1) { if (tid < st) red[tid] += red[tid + st]; __syncthreads(); }
        if (tid == 0) accC -= red[0];
        __syncthreads();
        red[tid] = vsum; __syncthreads();
        for (int st = 128; st; st >>= 1) { if (tid < st) red[tid] += red[tid + st]; __syncthreads(); }
        if (tid == 0) accV += red[0];
        __syncthreads();
    }

    if (tid == 0) {
        g_vc[t * 128 + c]      = accV * (1.f / 512.f);                          // V (mean over 8*64)
        g_vc[t * 128 + 64 + c] = accC * (1.f / (255.f * 255.f * 64.f * 8.f));   // C
    }
}

// ---------------- 5) batched Q@K^T with cosine + scalar bias epilogue ----------------
__global__ __launch_bounds__(256) void qk_kernel(
    const float* __restrict__ cov_logit, const float* __restrict__ var_logit)
{
    __shared__ float Qs[64 * 68];   // [k][n]
    __shared__ float Ks[64 * 68];   // [k][m]
    int tid = threadIdx.x;
    int hb = blockIdx.z, h = hb >> 6, b = hb & 63, c = hb >> 3;
    int nt = blockIdx.y, mt = blockIdx.x;
    int lr = tid >> 4, lc4 = tid & 15;

    const float* qb = g_f + (size_t)(b * 256 + nt * 64) * 512 + h * 64;
    const float* kb = g_f + FS + (size_t)(b * 256 + mt * 64) * 512 + h * 64;

    #pragma unroll
    for (int p = 0; p < 4; p++) {
        int row = lr + p * 16;
        float4 a = *(const float4*)(qb + (size_t)row * 512 + lc4 * 4);
        Qs[(lc4 * 4 + 0) * 68 + row] = a.x;
        Qs[(lc4 * 4 + 1) * 68 + row] = a.y;
        Qs[(lc4 * 4 + 2) * 68 + row] = a.z;
        Qs[(lc4 * 4 + 3) * 68 + row] = a.w;
        float4 kk = *(const float4*)(kb + (size_t)row * 512 + lc4 * 4);
        Ks[(lc4 * 4 + 0) * 68 + row] = kk.x;
        Ks[(lc4 * 4 + 1) * 68 + row] = kk.y;
        Ks[(lc4 * 4 + 2) * 68 + row] = kk.z;
        Ks[(lc4 * 4 + 3) * 68 + row] = kk.w;
    }
    __syncthreads();

    float acc[4][4] = {};
    #pragma unroll 16
    for (int k = 0; k < 64; k++) {
        float4 a  = *(const float4*)&Qs[k * 68 + lr * 4];
        float4 bb = *(const float4*)&Ks[k * 68 + lc4 * 4];
        acc[0][0] += a.x * bb.x; acc[0][1] += a.x * bb.y; acc[0][2] += a.x * bb.z; acc[0][3] += a.x * bb.w;
        acc[1][0] += a.y * bb.x; acc[1][1] += a.y * bb.y; acc[1][2] += a.y * bb.z; acc[1][3] += a.y * bb.w;
        acc[2][0] += a.z * bb.x; acc[2][1] += a.z * bb.y; acc[2][2] += a.z * bb.z; acc[2][3] += a.z * bb.w;
        acc[3][0] += a.w * bb.x; acc[3][1] += a.w * bb.y; acc[3][2] += a.w * bb.z; acc[3][3] += a.w * bb.w;
    }

    float cw = 1.f / (1.f + expf(-*cov_logit));
    float vw = 1.f / (1.f + expf(-*var_logit));
    float cosw = 1.f - cw - vw;
    float biasv = cw * (g_vc[64 + c] * g_vc[192 + c]) + vw * (g_vc[c] * g_vc[128 + c]);

    float qinv[4], kinv[4];
    #pragma unroll
    for (int r = 0; r < 4; r++) qinv[r] = 1.f / g_norms[hb * 256 + nt * 64 + lr * 4 + r];
    #pragma unroll
    for (int j = 0; j < 4; j++) kinv[j] = 1.f / g_norms[131072 + hb * 256 + mt * 64 + lc4 * 4 + j];

    float* sp = g_s + (size_t)hb * 65536;
    #pragma unroll
    for (int r = 0; r < 4; r++) {
        int n = nt * 64 + lr * 4 + r;
        float sc = cosw * qinv[r];
        float4 o = make_float4(sc * acc[r][0] * kinv[0] + biasv,
                               sc * acc[r][1] * kinv[1] + biasv,
                               sc * acc[r][2] * kinv[2] + biasv,
                               sc * acc[r][3] * kinv[3] + biasv);
        *(float4*)(sp + (size_t)n * 256 + mt * 64 + lc4 * 4) = o;
    }
}

// ---------------- 6) batched S@V, output scattered into [B,N,h*d] ----------------
__global__ __launch_bounds__(256) void sv_kernel()
{
    __shared__ float Ss[64 * 68];   // [m][n]  (S transposed)
    __shared__ float Vs[64 * 68];   // [m][dd]
    int tid = threadIdx.x;
    int hb = blockIdx.y, h = hb >> 6, b = hb & 63;
    int rt = blockIdx.x;
    int lr = tid >> 4, lc4 = tid & 15;

    const float* sp = g_s + (size_t)hb * 65536 + (size_t)(rt * 64) * 256;
    const float* vb = g_f + 2 * FS + (size_t)(b * 256) * 512 + h * 64;

    float acc[4][4] = {};
    for (int mc = 0; mc < 4; mc++) {
        #pragma unroll
        for (int p = 0; p < 4; p++) {
            int row = lr + p * 16;
            float4 a = *(const float4*)(sp + (size_t)row * 256 + mc * 64 + lc4 * 4);
            Ss[(lc4 * 4 + 0) * 68 + row] = a.x;
            Ss[(lc4 * 4 + 1) * 68 + row] = a.y;
            Ss[(lc4 * 4 + 2) * 68 + row] = a.z;
            Ss[(lc4 * 4 + 3) * 68 + row] = a.w;
            float4 vv = *(const float4*)(vb + (size_t)(mc * 64 + row) * 512 + lc4 * 4);
            *(float4*)&Vs[row * 68 + lc4 * 4] = vv;
        }
        __syncthreads();
        #pragma unroll 16
        for (int m = 0; m < 64; m++) {
            float4 a  = *(const float4*)&Ss[m * 68 + lr * 4];
            float4 bb = *(const float4*)&Vs[m * 68 + lc4 * 4];
            acc[0][0] += a.x * bb.x; acc[0][1] += a.x * bb.y; acc[0][2] += a.x * bb.z; acc[0][3] += a.x * bb.w;
            acc[1][0] += a.y * bb.x; acc[1][1] += a.y * bb.y; acc[1][2] += a.y * bb.z; acc[1][3] += a.y * bb.w;
            acc[2][0] += a.z * bb.x; acc[2][1] += a.z * bb.y; acc[2][2] += a.z * bb.z; acc[2][3] += a.z * bb.w;
            acc[3][0] += a.w * bb.x; acc[3][1] += a.w * bb.y; acc[3][2] += a.w * bb.z; acc[3][3] += a.w * bb.w;
        }
        __syncthreads();
    }

    float* ob = g_att + (size_t)(b * 256 + rt * 64) * 512 + h * 64;
    #pragma unroll
    for (int r = 0; r < 4; r++) {
        float4 o = make_float4(acc[r][0], acc[r][1], acc[r][2], acc[r][3]);
        *(float4*)(ob + (size_t)(lr * 4 + r) * 512 + lc4 * 4) = o;
    }
}

// ---------------- launch ----------------
extern "C" void kernel_launch(void* const* d_in, const int* in_sizes, int n_in,
                              void* d_out, int out_size)
{
    const float* q   = (const float*)d_in[0];
    const float* k   = (const float*)d_in[1];
    const float* v   = (const float*)d_in[2];
    const float* gma = (const float*)d_in[3];
    const float* bta = (const float*)d_in[4];
    const float* Win = (const float*)d_in[5];
    const float* Wout= (const float*)d_in[6];
    const float* bout= (const float*)d_in[7];
    const float* covl= (const float*)d_in[8];
    const float* varl= (const float*)d_in[9];
    float* out = (float*)d_out;

    void *pxn, *pf, *patt;
    cudaGetSymbolAddress(&pxn, g_xn);
    cudaGetSymbolAddress(&pf, g_f);
    cudaGetSymbolAddress(&patt, g_att);

    ln_kernel<<<6144, 256>>>(q, k, v, gma, bta);
    sgemm_kernel<<<dim3(4, 384), 256>>>((const float*)pxn, Win, (float*)pf, nullptr);
    norm_kernel<<<32768, 256>>>();
    stats_kernel<<<128, 256>>>();
    qk_kernel<<<dim3(4, 4, 512), 256>>>(covl, varl);
    sv_kernel<<<dim3(4, 512), 256>>>();
    sgemm_kernel<<<dim3(4, 128), 256>>>((const float*)patt, Wout, out, bout);
}